// round 17
// baseline (speedup 1.0000x reference)
#include <cuda_runtime.h>
#include <cuda_bf16.h>
#include <cstdint>

// ---------------- problem dims (fixed by dataset) ----------------
#define T_STEPS 512
#define BATCH   128
#define SDIM    1024
#define ODIM    256
#define JDIM    (SDIM + ODIM)   // 1280

// ---------------- tiling ----------------
#define NB 4                 // batch tiles (independent recurrence groups)
#define NJ 32                // j tiles
#define BT 32                // batch rows per CTA
#define JT 40                // j cols per CTA
#define NCTAS (NB * NJ)      // 128 CTAs, one per SM
#define NTHREADS 256
#define NWARPS 8
#define CLUSTER 4
#define ROWS_PER_CTA (BT / CLUSTER)   // 8 rows loaded+multicast per CTA
#define PAD 8
#define GSTRIDE (SDIM + PAD) // 1032 halves per smem G row
#define ROW_BYTES (SDIM * 2) // 2048 B per G row in gmem
#define NPROD 26             // jtiles 0..25 produce h columns
// row-split: warps 0-3 rows 0-15 (K quarter = warp&3), warps 4-7 rows 16-31
#define KQ 256               // K elems per warp
#define EHALF 640            // 16*40 elements per half
// pre-swizzled smem W (upper k-half of each quarter): 4*8*5*32 uint2 pairs
#define SW_PAIRS 5120
// per-warp release slots: [half][btile][warp-in-half][jtile]
#define SLOT_HALF (NB * 128)

// smem layout (bytes)
#define SG_BYTES (BT * GSTRIDE * 2)            // 66048
#define SW_BYTES (SW_PAIRS * 8)                // 40960
#define SP_BYTES (NWARPS * EHALF * 4)          // 20480
#define SMEM_TOTAL (SG_BYTES + SW_BYTES + SP_BYTES + 16)

// ---------------- device globals ----------------
__device__ __align__(16) __nv_bfloat16 g_W[(size_t)JDIM * SDIM];
__device__ __align__(16) __nv_bfloat16 g_G[2][(size_t)BATCH * SDIM];
__device__ unsigned g_slotsW[2 * SLOT_HALF];   // per-warp arrival slots

// ---------------- helpers ----------------
__device__ __forceinline__ unsigned ld_acq(const unsigned* p) {
    unsigned v;
    asm volatile("ld.acquire.gpu.global.u32 %0, [%1];" : "=r"(v) : "l"(p));
    return v;
}
__device__ __forceinline__ void st_rel(unsigned* p, unsigned v) {
    asm volatile("st.release.gpu.global.u32 [%0], %1;" :: "l"(p), "r"(v) : "memory");
}
__device__ __forceinline__ float tanh_fast(float v) {
    float r;
    asm("tanh.approx.f32 %0, %1;" : "=f"(r) : "f"(v));
    return r;
}
__device__ __forceinline__ void mma16816(float c[4], const unsigned a[4],
                                         unsigned b0, unsigned b1) {
    asm volatile(
        "mma.sync.aligned.m16n8k16.row.col.f32.bf16.bf16.f32 "
        "{%0,%1,%2,%3}, {%4,%5,%6,%7}, {%8,%9}, {%0,%1,%2,%3};\n"
        : "+f"(c[0]), "+f"(c[1]), "+f"(c[2]), "+f"(c[3])
        : "r"(a[0]), "r"(a[1]), "r"(a[2]), "r"(a[3]), "r"(b0), "r"(b1));
}
__device__ __forceinline__ void ldsm_x4(unsigned a[4], uint32_t addr) {
    asm volatile("ldmatrix.sync.aligned.m8n8.x4.shared.b16 {%0,%1,%2,%3}, [%4];"
                 : "=r"(a[0]), "=r"(a[1]), "=r"(a[2]), "=r"(a[3]) : "r"(addr));
}
__device__ __forceinline__ void mbar_wait(uint32_t mbar, unsigned parity) {
    asm volatile(
        "{\n\t"
        ".reg .pred P;\n\t"
        "WL_%=:\n\t"
        "mbarrier.try_wait.parity.acquire.cta.shared::cta.b64 P, [%0], %1, 0x989680;\n\t"
        "@P bra.uni WD_%=;\n\t"
        "bra.uni WL_%=;\n\t"
        "WD_%=:\n\t"
        "}" :: "r"(mbar), "r"(parity) : "memory");
}
__device__ __forceinline__ void bar_named(int id) {
    asm volatile("bar.sync %0, 128;" :: "r"(id) : "memory");
}

// ---------------- init ----------------
__global__ void trnn_init(const float* __restrict__ w_r, const float* __restrict__ w_o,
                          const float* __restrict__ h_init) {
    size_t stride = (size_t)gridDim.x * blockDim.x;
    size_t i0 = (size_t)blockIdx.x * blockDim.x + threadIdx.x;
    const size_t WR_N = (size_t)SDIM * SDIM;
    const size_t W_N  = (size_t)JDIM * SDIM;
    for (size_t i = i0; i < W_N; i += stride) {
        float v = (i < WR_N) ? w_r[i] : w_o[i - WR_N];
        g_W[i] = __float2bfloat16(v);
    }
    for (size_t i = i0; i < (size_t)BATCH * SDIM; i += stride) {
        g_G[0][i] = __float2bfloat16(tanhf(h_init[i]));
    }
    if (i0 < 2 * SLOT_HALF) g_slotsW[i0] = 0u;
}

// ---------------- persistent kernel: row-owned halves + per-warp release (no barB) ----------------
__global__ void __launch_bounds__(NTHREADS, 1) __cluster_dims__(CLUSTER, 1, 1)
trnn_persistent(const float* __restrict__ x, const float* __restrict__ h_init,
                const float* __restrict__ b_r, const float* __restrict__ b_o,
                float* __restrict__ out) {
    extern __shared__ char smem[];
    __nv_bfloat16* sG = (__nv_bfloat16*)smem;
    uint2* sW64 = (uint2*)(smem + SG_BYTES);
    float* sP = (float*)(smem + SG_BYTES + SW_BYTES);
    uint32_t mbar0 = (uint32_t)__cvta_generic_to_shared(smem + SG_BYTES + SW_BYTES + SP_BYTES);
    uint32_t mbar1 = mbar0 + 8;

    const int tid  = threadIdx.x;
    const int warp = tid >> 5;
    const int lane = tid & 31;
    const int grp  = lane >> 2;
    const int tig  = lane & 3;
    const int btile = blockIdx.x >> 5;
    const int jtile = blockIdx.x & 31;
    const int rank  = blockIdx.x & (CLUSTER - 1);
    const int b0 = btile * BT;
    const int j0 = jtile * JT;
    const int kq = warp & 3;             // K quarter [kq*256, kq*256+256)
    const int half = warp >> 2;          // 0: rows 0-15, 1: rows 16-31
    const int mybar = 1 + half;          // named barrier id (barrier A only)
    const bool producer = (jtile < NPROD);
    const int pollwarp = (rank < 2) ? 0 : 4;

    // slot bases: gating half for this rank's TMA rows; own release slot
    unsigned* poll_base = &g_slotsW[((rank < 2) ? 0 : 1) * SLOT_HALF + btile * 128];
    unsigned* my_half_base = &g_slotsW[half * SLOT_HALF + btile * 128];
    unsigned* my_slot = &my_half_base[kq * 32 + jtile];
    const uint32_t my_mbar  = (rank < 2) ? mbar0 : mbar1;
    const uint32_t half_mbar = half ? mbar1 : mbar0;

    if (tid == 0) {
        asm volatile("mbarrier.init.shared.b64 [%0], 1;" :: "r"(mbar0) : "memory");
        asm volatile("mbarrier.init.shared.b64 [%0], 1;" :: "r"(mbar1) : "memory");
    }
    __syncthreads();
    asm volatile("barrier.cluster.arrive.aligned;" ::: "memory");
    asm volatile("barrier.cluster.wait.aligned;"   ::: "memory");

    // --- per-thread epilogue state: threads 0-127 own rows 0-15, 128-255 rows 16-31 ---
    const int tl = tid & 127;
    const int rowoff = (tid >> 7) * 16;
    int ej[5]; int erow[5]; float hr[5]; float bv[5];
    #pragma unroll
    for (int d = 0; d < 5; ++d) {
        int e = d * 128 + tl;
        int r = rowoff + e / JT;
        int j = j0 + (e % JT);
        ej[d] = j; erow[d] = r;
        if (j < SDIM) {
            hr[d] = h_init[(size_t)(b0 + r) * SDIM + j];
            bv[d] = b_r[j];
        } else {
            hr[d] = 0.f;
            bv[d] = b_o[j - SDIM];
        }
    }

    // --- W k-steps 0-7 of my quarter: registers (80 regs) ---
    unsigned Breg[8][5][2];
    #pragma unroll
    for (int ks = 0; ks < 8; ++ks) {
        #pragma unroll
        for (int ni = 0; ni < 5; ++ni) {
            int jr = j0 + ni * 8 + grp;
            const unsigned* wp = (const unsigned*)(g_W + (size_t)jr * SDIM + kq * KQ + ks * 16);
            Breg[ks][ni][0] = wp[tig];
            Breg[ks][ni][1] = wp[4 + tig];
        }
    }
    // --- W upper k-half of every quarter: pre-swizzled pairs, slot = lane (bank-clean) ---
    for (int i = tid; i < SW_PAIRS; i += NTHREADS) {
        int kq_ = i / 1280;
        int rem = i - kq_ * 1280;
        int ks_ = rem / 160;
        int rem2 = rem - ks_ * 160;
        int ni_ = rem2 >> 5;
        int sl = rem2 & 31;
        int grp_s = sl >> 2, tig_s = sl & 3;
        int jr = j0 + ni_ * 8 + grp_s;
        const unsigned* wp = (const unsigned*)(g_W + (size_t)jr * SDIM + kq_ * KQ + 128 + ks_ * 16);
        sW64[i] = make_uint2(wp[tig_s], wp[4 + tig_s]);
    }
    __syncthreads();

    const uint32_t sGb = (uint32_t)__cvta_generic_to_shared(sG);
    const int rl = lane & 15;
    const uint32_t aBase = sGb
        + (uint32_t)(((half * 16 + rl) * GSTRIDE + kq * KQ) * 2 + ((lane & 16) ? 16 : 0));
    const uint2* myW = sW64 + (size_t)kq * 1280 + lane;

    for (int it = 0; it <= T_STEPS; ++it) {
        const unsigned parity = (unsigned)(it & 1);

        // --- expect_tx: warp0 -> mbar0, warp4 -> mbar1 ---
        if (tid == 0)
            asm volatile("mbarrier.arrive.expect_tx.shared.b64 _, [%0], %1;"
                         :: "r"(mbar0), "r"(16 * ROW_BYTES) : "memory");
        if (tid == 128)
            asm volatile("mbarrier.arrive.expect_tx.shared.b64 _, [%0], %1;"
                         :: "r"(mbar1), "r"(16 * ROW_BYTES) : "memory");

        // --- x prefetch (off critical path) ---
        float xr[5];
        if (it >= 1) {
            #pragma unroll
            for (int d = 0; d < 5; ++d)
                if (ej[d] >= SDIM) {
                    size_t oi = ((size_t)(it - 1) * BATCH + (b0 + erow[d])) * ODIM + (ej[d] - SDIM);
                    xr[d] = __ldcs(x + oi);
                }
        }

        // --- aligned poll warp: poll 4 per-warp slot arrays, lanes 0-7 issue multicasts ---
        if (warp == pollwarp) {
            if (it > 0) {
                const unsigned phase = (unsigned)it;
                for (;;) {
                    unsigned v0 = ld_acq(&poll_base[lane]);
                    unsigned v1 = ld_acq(&poll_base[32 + lane]);
                    unsigned v2 = ld_acq(&poll_base[64 + lane]);
                    unsigned v3 = ld_acq(&poll_base[96 + lane]);
                    bool ok = (v0 >= phase) & (v1 >= phase) & (v2 >= phase) & (v3 >= phase);
                    if (__all_sync(0xffffffffu, ok)) break;
                }
            }
            if (lane < ROWS_PER_CTA) {
                const __nv_bfloat16* Gc = g_G[it & 1];
                asm volatile("fence.proxy.async;" ::: "memory");
                int r = rank * ROWS_PER_CTA + lane;
                const void* src = (const void*)(Gc + (size_t)(b0 + r) * SDIM);
                uint32_t dst = (uint32_t)__cvta_generic_to_shared(sG + r * GSTRIDE);
                asm volatile(
                    "cp.async.bulk.shared::cluster.global.mbarrier::complete_tx::bytes"
                    ".multicast::cluster [%0], [%1], %2, [%3], %4;"
                    :: "r"(dst), "l"(src), "r"(ROW_BYTES), "r"(my_mbar),
                       "h"((unsigned short)((1u << CLUSTER) - 1u))
                    : "memory");
            }
        }

        // --- wait only this warp's row-half; mma over full K quarter (16 k-steps) ---
        mbar_wait(half_mbar, parity);

        float acc[5][4];
        #pragma unroll
        for (int ni = 0; ni < 5; ++ni)
            #pragma unroll
            for (int q = 0; q < 4; ++q) acc[ni][q] = 0.f;

        #pragma unroll
        for (int ks = 0; ks < 8; ++ks) {        // k-steps 0-7: W in registers
            unsigned a[4];
            ldsm_x4(a, aBase + ks * 32);
            #pragma unroll
            for (int ni = 0; ni < 5; ++ni)
                mma16816(acc[ni], a, Breg[ks][ni][0], Breg[ks][ni][1]);
        }
        #pragma unroll
        for (int ks = 0; ks < 8; ++ks) {        // k-steps 8-15: W via conflict-free LDS.64
            unsigned a[4];
            ldsm_x4(a, aBase + 256 + ks * 32);
            #pragma unroll
            for (int ni = 0; ni < 5; ++ni) {
                uint2 w = myW[ks * 160 + ni * 32];
                mma16816(acc[ni], a, w.x, w.y);
            }
        }

        // --- partials: slot `warp` holds this warp's 16x40 tile ---
        {
            float* p = sP + warp * EHALF;
            #pragma unroll
            for (int ni = 0; ni < 5; ++ni) {
                int cc = ni * 8 + tig * 2;
                *(float2*)&p[grp * JT + cc]       = make_float2(acc[ni][0], acc[ni][1]);
                *(float2*)&p[(grp + 8) * JT + cc] = make_float2(acc[ni][2], acc[ni][3]);
            }
        }
        bar_named(mybar);   // barrier A: my half's partials in, my half's sG reads done

        // non-producers: nothing to store -> release all 4 warp slots of my half now
        if (!producer) {
            if (tid == 0) {
                #pragma unroll
                for (int w = 0; w < 4; ++w)
                    st_rel(&g_slotsW[0 * SLOT_HALF + btile * 128 + w * 32 + jtile],
                           (unsigned)(it + 1));
            }
            if (tid == 128) {
                #pragma unroll
                for (int w = 0; w < 4; ++w)
                    st_rel(&g_slotsW[1 * SLOT_HALF + btile * 128 + w * 32 + jtile],
                           (unsigned)(it + 1));
            }
        }

        // --- 4-partial reduce + h update + tanh + G store (within my half) ---
        __nv_bfloat16* Gn = g_G[(it + 1) & 1];
        const float* pb = sP + (half * 4) * EHALF;
        float yv[5];
        #pragma unroll
        for (int d = 0; d < 5; ++d) {
            int e = d * 128 + tl;
            float y = (pb[e] + pb[EHALF + e]) + (pb[2 * EHALF + e] + pb[3 * EHALF + e]);
            yv[d] = y;
            if (ej[d] < SDIM) {
                float hv = 0.75f * hr[d] + 0.25f * (y + bv[d]);
                hr[d] = hv;
                Gn[(size_t)(b0 + erow[d]) * SDIM + ej[d]] = __float2bfloat16(tanh_fast(hv));
            }
        }

        // producers: per-warp release right after own epilogue portion (no barrier B)
        if (producer) {
            __syncwarp();
            if (lane == 0) st_rel(my_slot, (unsigned)(it + 1));
        }

        // --- outputs (off the critical path) ---
        if (it >= 1) {
            #pragma unroll
            for (int d = 0; d < 5; ++d)
                if (ej[d] >= SDIM) {
                    size_t oi = ((size_t)(it - 1) * BATCH + (b0 + erow[d])) * ODIM + (ej[d] - SDIM);
                    out[oi] = yv[d] + bv[d] - xr[d];
                }
        }
    }

    __syncthreads();
    asm volatile("barrier.cluster.arrive.aligned;" ::: "memory");
    asm volatile("barrier.cluster.wait.aligned;"   ::: "memory");
}

// ---------------- launch ----------------
extern "C" void kernel_launch(void* const* d_in, const int* in_sizes, int n_in,
                              void* d_out, int out_size) {
    const float *x = nullptr, *h = nullptr, *wr = nullptr, *br = nullptr,
                *wo = nullptr, *bo = nullptr;
    for (int i = 0; i < n_in; ++i) {
        switch (in_sizes[i]) {
            case 512 * 128 * 256: x  = (const float*)d_in[i]; break;
            case 128 * 1024:      h  = (const float*)d_in[i]; break;
            case 1024 * 1024:     wr = (const float*)d_in[i]; break;
            case 1024:            br = (const float*)d_in[i]; break;
            case 256 * 1024:      wo = (const float*)d_in[i]; break;
            case 256:             bo = (const float*)d_in[i]; break;
            default: break;
        }
    }
    cudaFuncSetAttribute(trnn_persistent,
                         cudaFuncAttributeMaxDynamicSharedMemorySize, SMEM_TOTAL);
    trnn_init<<<512, 256>>>(wr, wo, h);
    trnn_persistent<<<NCTAS, NTHREADS, SMEM_TOTAL>>>(x, h, br, bo, (float*)d_out);
}